// round 10
// baseline (speedup 1.0000x reference)
#include <cuda_runtime.h>
#include <cstdint>

#define TT    25088
#define ED    768
#define NHEAD 12
#define HDIM  64
#define NTOK  196
#define MLPD  3072

// fp32 (tf32-rounded) pipeline buffers.
// Lifetime-based aliasing to minimize static device footprint:
//   g_y   : LN1 out (dead after QKV GEMM) -> reused as LN2 out
//   g_hh  : MLP hidden (dead until MLP1)  -> front TT*ED floats reused as attn out
__device__ float g_y  [(size_t)TT * ED];
__device__ float g_qkv[(size_t)TT * 2304];
__device__ float g_x1 [(size_t)TT * ED];
__device__ float g_hh [(size_t)TT * MLPD];
__device__ float g_wqkv [768 * 2304];
__device__ float g_wproj[768 * 768];
__device__ float g_w1   [768 * 3072];
__device__ float g_w2   [3072 * 768];

__device__ __forceinline__ uint32_t smem_u32(const void* p) {
    return (uint32_t)__cvta_generic_to_shared(p);
}
__device__ __forceinline__ float tf32r(float x) {
    asm("cvt.rna.tf32.f32 %0,%1;\n" : "=f"(x) : "f"(x));
    return x;
}
__device__ __forceinline__ void mma_tf32(float* c, const float* a, const float* b) {
    asm volatile(
        "mma.sync.aligned.m16n8k8.row.col.f32.tf32.tf32.f32 "
        "{%0,%1,%2,%3},{%4,%5,%6,%7},{%8,%9},{%0,%1,%2,%3};\n"
        : "+f"(c[0]), "+f"(c[1]), "+f"(c[2]), "+f"(c[3])
        : "r"(__float_as_uint(a[0])), "r"(__float_as_uint(a[1])),
          "r"(__float_as_uint(a[2])), "r"(__float_as_uint(a[3])),
          "r"(__float_as_uint(b[0])), "r"(__float_as_uint(b[1])));
}
__device__ __forceinline__ void cpasync16(void* s, const void* g) {
    asm volatile("cp.async.cg.shared.global [%0],[%1],16;\n" ::"r"(smem_u32(s)), "l"(g));
}
__device__ __forceinline__ void cp_commit() { asm volatile("cp.async.commit_group;\n"); }
__device__ __forceinline__ void cp_wait0()  { asm volatile("cp.async.wait_group 0;\n"); }

__device__ __forceinline__ int tok_to_winrow(int t) {
    int img = t / 3136; int rem = t - img * 3136;
    int r = rem / 56, c = rem - r * 56;
    return (img * 16 + (r / 14) * 4 + (c / 14)) * NTOK + (r % 14) * 14 + (c % 14);
}
__device__ __forceinline__ int winrow_to_tok(int rr) {
    int w = rr / NTOK, p = rr - w * NTOK;
    int img = w >> 4; int wi = w & 15;
    return img * 3136 + ((wi >> 2) * 14 + p / 14) * 56 + (wi & 3) * 14 + p % 14;
}

__global__ void cvt_kernel(const float* __restrict__ s, float* __restrict__ d, int n) {
    for (int i = blockIdx.x * blockDim.x + threadIdx.x; i < n; i += gridDim.x * blockDim.x)
        d[i] = tf32r(s[i]);
}

__global__ __launch_bounds__(256) void ln_kernel(const float* __restrict__ x,
                                                 const float* __restrict__ w,
                                                 const float* __restrict__ b,
                                                 float* __restrict__ out, int permute) {
    int row = blockIdx.x;
    const float* xr = x + (size_t)row * ED;
    int t = threadIdx.x;
    float v0 = xr[t], v1 = xr[t + 256], v2 = xr[t + 512];
    float s = v0 + v1 + v2;
    float q = v0 * v0 + v1 * v1 + v2 * v2;
#pragma unroll
    for (int o = 16; o; o >>= 1) {
        s += __shfl_xor_sync(0xffffffffu, s, o);
        q += __shfl_xor_sync(0xffffffffu, q, o);
    }
    __shared__ float ss[8], sq[8], smu, srs;
    if ((t & 31) == 0) { ss[t >> 5] = s; sq[t >> 5] = q; }
    __syncthreads();
    if (t == 0) {
        float S = 0.f, Q = 0.f;
#pragma unroll
        for (int i = 0; i < 8; i++) { S += ss[i]; Q += sq[i]; }
        float mu = S * (1.f / ED);
        smu = mu; srs = rsqrtf(Q * (1.f / ED) - mu * mu + 1e-5f);
    }
    __syncthreads();
    float mu = smu, rs = srs;
    int drow = permute ? tok_to_winrow(row) : row;
    float* o = out + (size_t)drow * ED;
    o[t]       = tf32r((v0 - mu) * rs * w[t]       + b[t]);
    o[t + 256] = tf32r((v1 - mu) * rs * w[t + 256] + b[t + 256]);
    o[t + 512] = tf32r((v2 - mu) * rs * w[t + 512] + b[t + 512]);
}

// ---------------- tf32 GEMM 128x128x16, double buffered ----------------
#define BM 128
#define BN 128
#define BK 16
#define ASTR 20     // 4*5 -> conflict-free for rows=lane>>2, col=lane&3
#define BSTR 136    // 8*17 -> conflict-free for rows=lane&3, col=lane>>2
#define EPI_QKV  0
#define EPI_PROJ 1
#define EPI_MLP1 2
#define EPI_MLP2 3

template <int EPI>
__global__ __launch_bounds__(256) void gemm_kernel(
    const float* __restrict__ A, const float* __restrict__ B,
    const float* __restrict__ bias, const float* __restrict__ res,
    float* __restrict__ out, int M, int N, int K) {
    __shared__ __align__(16) float a_s[2][BM][ASTR];
    __shared__ __align__(16) float b_s[2][BK][BSTR];
    int bm = blockIdx.x * BM, bn = blockIdx.y * BN;
    int tid = threadIdx.x, lane = tid & 31, wid = tid >> 5;
    int wm = (wid >> 2) * 64, wn = (wid & 3) * 32;

    float acc[4][4][4];
#pragma unroll
    for (int i = 0; i < 4; i++)
#pragma unroll
        for (int j = 0; j < 4; j++)
#pragma unroll
            for (int r = 0; r < 4; r++) acc[i][j][r] = 0.f;

    auto load_tiles = [&](int k0, int buf) {
#pragma unroll
        for (int i = 0; i < 2; i++) {
            int c = tid * 2 + i;           // 512 chunks of 4 floats
            int ra = c >> 2, kc = c & 3;   // A: 128 rows x 4 chunks
            cpasync16(&a_s[buf][ra][kc * 4], A + (size_t)(bm + ra) * K + k0 + kc * 4);
        }
#pragma unroll
        for (int i = 0; i < 2; i++) {
            int c = tid * 2 + i;
            int kr = c >> 5, nc = c & 31;  // B: 16 rows x 32 chunks
            cpasync16(&b_s[buf][kr][nc * 4], B + (size_t)(k0 + kr) * N + bn + nc * 4);
        }
        cp_commit();
    };

    load_tiles(0, 0);
    int KT = K / BK, buf = 0;
    int r0 = lane >> 2, cc = lane & 3;
    for (int kt = 0; kt < KT; kt++) {
        cp_wait0();
        __syncthreads();
        if (kt + 1 < KT) load_tiles((kt + 1) * BK, buf ^ 1);
#pragma unroll
        for (int kk = 0; kk < BK; kk += 8) {
            float aF[4][4], bF[4][2];
#pragma unroll
            for (int mf = 0; mf < 4; mf++) {
                int rr = wm + mf * 16 + r0;
                aF[mf][0] = a_s[buf][rr][kk + cc];
                aF[mf][1] = a_s[buf][rr + 8][kk + cc];
                aF[mf][2] = a_s[buf][rr][kk + cc + 4];
                aF[mf][3] = a_s[buf][rr + 8][kk + cc + 4];
            }
#pragma unroll
            for (int nf = 0; nf < 4; nf++) {
                int nn = wn + nf * 8 + r0;
                bF[nf][0] = b_s[buf][kk + cc][nn];
                bF[nf][1] = b_s[buf][kk + cc + 4][nn];
            }
#pragma unroll
            for (int mf = 0; mf < 4; mf++)
#pragma unroll
                for (int nf = 0; nf < 4; nf++) mma_tf32(acc[mf][nf], aF[mf], bF[nf]);
        }
        buf ^= 1;
        __syncthreads();
    }

#pragma unroll
    for (int mf = 0; mf < 4; mf++)
#pragma unroll
        for (int nf = 0; nf < 4; nf++) {
            int row0 = bm + wm + mf * 16 + (lane >> 2);
            int col = bn + wn + nf * 8 + (lane & 3) * 2;
            float bi0 = bias[col], bi1 = bias[col + 1];
#pragma unroll
            for (int h = 0; h < 2; h++) {
                int row = row0 + h * 8;
                float v0 = acc[mf][nf][h * 2 + 0] + bi0;
                float v1 = acc[mf][nf][h * 2 + 1] + bi1;
                if (EPI == EPI_QKV) {
                    *reinterpret_cast<float2*>(&out[(size_t)row * N + col]) =
                        make_float2(tf32r(v0), tf32r(v1));
                } else if (EPI == EPI_MLP1) {
                    float g0 = 0.5f * v0 * (1.f + erff(v0 * 0.70710678f));
                    float g1 = 0.5f * v1 * (1.f + erff(v1 * 0.70710678f));
                    *reinterpret_cast<float2*>(&out[(size_t)row * N + col]) =
                        make_float2(tf32r(g0), tf32r(g1));
                } else if (EPI == EPI_PROJ) {
                    size_t o = (size_t)winrow_to_tok(row) * ED + col;
                    float2 rv = *reinterpret_cast<const float2*>(res + o);
                    *reinterpret_cast<float2*>(&out[o]) = make_float2(rv.x + v0, rv.y + v1);
                } else {
                    size_t o = (size_t)row * ED + col;
                    float2 rv = *reinterpret_cast<const float2*>(res + o);
                    *reinterpret_cast<float2*>(&out[o]) = make_float2(rv.x + v0, rv.y + v1);
                }
            }
        }
}

// ---------------- fused windowed attention, tf32 ----------------
#define QSTR 68   // 4*17: rows by lane>>2 pattern
#define KSTR 68
#define VSTR 72   // 8*9: rows by lane&3 pattern
#define PSTR 260  // 4*65
#define OFF_K   (64 * QSTR * 4)
#define OFF_V   (OFF_K + 256 * KSTR * 4)
#define OFF_RH  (OFF_V + 256 * VSTR * 4)
#define OFF_RW  (OFF_RH + 64 * 14 * 4)
#define OFF_RED (OFF_RW + 64 * 14 * 4)
#define OFF_RM  (OFF_RED + 64 * 8 * 4)
#define OFF_RS  (OFF_RM + 64 * 4)
#define ATT_SMEM (OFF_RS + 64 * 4)

__global__ __launch_bounds__(256) void attn_kernel(const float* __restrict__ relh_tab,
                                                   const float* __restrict__ relw_tab,
                                                   float* __restrict__ ao) {
    extern __shared__ char smem[];
    float* Qs = (float*)smem;
    float* Ks = (float*)(smem + OFF_K);
    float* Vs = (float*)(smem + OFF_V);
    float* relh = (float*)(smem + OFF_RH);
    float* relw = (float*)(smem + OFF_RW);
    float* red = (float*)(smem + OFF_RED);
    float* rowmax = (float*)(smem + OFF_RM);
    float* rowsum = (float*)(smem + OFF_RS);
    float* Ps = Ks;  // 64*260 floats <= 256*68 floats

    int qt = blockIdx.x, wh = blockIdx.y;
    int w = wh / NHEAD, h = wh - w * NHEAD;
    int tid = threadIdx.x, lane = tid & 31, wid = tid >> 5;
    size_t base = (size_t)w * NTOK * 2304 + h * HDIM;

    // Q: 64 rows x 64 floats
    for (int c = tid; c < 1024; c += 256) {
        int r = c >> 4, ch = c & 15;
        int qi = qt * 64 + r;
        float4 val = make_float4(0.f, 0.f, 0.f, 0.f);
        if (qi < NTOK)
            val = *reinterpret_cast<const float4*>(&g_qkv[base + (size_t)qi * 2304 + ch * 4]);
        *reinterpret_cast<float4*>(&Qs[r * QSTR + ch * 4]) = val;
    }
    // K,V: 256 rows (zero-padded beyond 196)
    for (int c = tid; c < 4096; c += 256) {
        int r = c >> 4, ch = c & 15;
        float4 kv = make_float4(0.f, 0.f, 0.f, 0.f), vv = kv;
        if (r < NTOK) {
            kv = *reinterpret_cast<const float4*>(&g_qkv[base + (size_t)r * 2304 + 768 + ch * 4]);
            vv = *reinterpret_cast<const float4*>(&g_qkv[base + (size_t)r * 2304 + 1536 + ch * 4]);
        }
        *reinterpret_cast<float4*>(&Ks[r * KSTR + ch * 4]) = kv;
        *reinterpret_cast<float4*>(&Vs[r * VSTR + ch * 4]) = vv;
    }
    __syncthreads();

    // decomposed rel-pos: relh[i][kh] = q_i . Rh[qh-kh+13]
    for (int id = tid; id < 1792; id += 256) {
        int tab = id >= 896;
        int lid = tab ? id - 896 : id;
        int i = lid / 14, kx = lid - 14 * i;
        int qi = qt * 64 + i;
        float sum = 0.f;
        if (qi < NTOK) {
            int qh = qi / 14, qw = qi - qh * 14;
            int ridx = (tab ? qw : qh) - kx + 13;
            const float* tp = (tab ? relw_tab : relh_tab) + ridx * HDIM;
#pragma unroll 8
            for (int d = 0; d < HDIM; d++) sum += Qs[i * QSTR + d] * tp[d];
        }
        (tab ? relw : relh)[i * 14 + kx] = sum;
    }
    __syncthreads();

    // S = Q K^T : warp owns 32 key columns
    float sacc[4][4][4];
#pragma unroll
    for (int i = 0; i < 4; i++)
#pragma unroll
        for (int j = 0; j < 4; j++)
#pragma unroll
            for (int r = 0; r < 4; r++) sacc[i][j][r] = 0.f;
    int n0 = wid * 32;
    int r0 = lane >> 2, cc = lane & 3;
#pragma unroll
    for (int kk = 0; kk < HDIM; kk += 8) {
        float aF[4][4], bF[4][2];
#pragma unroll
        for (int mf = 0; mf < 4; mf++) {
            int rr = mf * 16 + r0;
            aF[mf][0] = Qs[rr * QSTR + kk + cc];
            aF[mf][1] = Qs[(rr + 8) * QSTR + kk + cc];
            aF[mf][2] = Qs[rr * QSTR + kk + cc + 4];
            aF[mf][3] = Qs[(rr + 8) * QSTR + kk + cc + 4];
        }
#pragma unroll
        for (int nf = 0; nf < 4; nf++) {
            int key = n0 + nf * 8 + r0;
            bF[nf][0] = Ks[key * KSTR + kk + cc];
            bF[nf][1] = Ks[key * KSTR + kk + cc + 4];
        }
#pragma unroll
        for (int mf = 0; mf < 4; mf++)
#pragma unroll
            for (int nf = 0; nf < 4; nf++) mma_tf32(sacc[mf][nf], aF[mf], bF[nf]);
    }

    const float scale = 0.125f;
#pragma unroll
    for (int mf = 0; mf < 4; mf++)
#pragma unroll
        for (int nf = 0; nf < 4; nf++)
#pragma unroll
            for (int r = 0; r < 4; r++) {
                int i = mf * 16 + (lane >> 2) + (r >> 1) * 8;
                int j = n0 + nf * 8 + (lane & 3) * 2 + (r & 1);
                float s;
                if (j < NTOK) {
                    int kh = j / 14, kw = j - kh * 14;
                    s = sacc[mf][nf][r] * scale + relh[i * 14 + kh] + relw[i * 14 + kw];
                } else s = -1e30f;
                sacc[mf][nf][r] = s;
            }

#pragma unroll
    for (int mf = 0; mf < 4; mf++)
#pragma unroll
        for (int rh = 0; rh < 2; rh++) {
            float m = -1e30f;
#pragma unroll
            for (int nf = 0; nf < 4; nf++) {
                m = fmaxf(m, sacc[mf][nf][rh * 2]);
                m = fmaxf(m, sacc[mf][nf][rh * 2 + 1]);
            }
            m = fmaxf(m, __shfl_xor_sync(0xffffffffu, m, 1));
            m = fmaxf(m, __shfl_xor_sync(0xffffffffu, m, 2));
            if ((lane & 3) == 0) red[(mf * 16 + (lane >> 2) + rh * 8) * 8 + wid] = m;
        }
    __syncthreads();
    if (tid < 64) {
        float m = red[tid * 8];
#pragma unroll
        for (int k = 1; k < 8; k++) m = fmaxf(m, red[tid * 8 + k]);
        rowmax[tid] = m;
    }
    __syncthreads();

#pragma unroll
    for (int mf = 0; mf < 4; mf++)
#pragma unroll
        for (int rh = 0; rh < 2; rh++) {
            int i = mf * 16 + (lane >> 2) + rh * 8;
            float rm = rowmax[i], s = 0.f;
#pragma unroll
            for (int nf = 0; nf < 4; nf++) {
                float p0 = __expf(sacc[mf][nf][rh * 2] - rm);
                float p1 = __expf(sacc[mf][nf][rh * 2 + 1] - rm);
                s += p0 + p1;
                int j = n0 + nf * 8 + (lane & 3) * 2;
                *reinterpret_cast<float2*>(&Ps[i * PSTR + j]) =
                    make_float2(tf32r(p0), tf32r(p1));
            }
            s += __shfl_xor_sync(0xffffffffu, s, 1);
            s += __shfl_xor_sync(0xffffffffu, s, 2);
            if ((lane & 3) == 0) red[i * 8 + wid] = s;
        }
    __syncthreads();
    if (tid < 64) {
        float s = 0.f;
#pragma unroll
        for (int k = 0; k < 8; k++) s += red[tid * 8 + k];
        rowsum[tid] = s;
    }
    __syncthreads();

    // O = P @ V : warp tile [16 q-rows, 32 head-dims]
    float oacc[4][4];
#pragma unroll
    for (int i = 0; i < 4; i++)
#pragma unroll
        for (int r = 0; r < 4; r++) oacc[i][r] = 0.f;
    int mo = (wid & 3) * 16, nh2 = (wid >> 2) * 32;
#pragma unroll 8
    for (int kk = 0; kk < 256; kk += 8) {
        float aF[4], bF[4][2];
        int rr = mo + r0;
        aF[0] = Ps[rr * PSTR + kk + cc];
        aF[1] = Ps[(rr + 8) * PSTR + kk + cc];
        aF[2] = Ps[rr * PSTR + kk + cc + 4];
        aF[3] = Ps[(rr + 8) * PSTR + kk + cc + 4];
#pragma unroll
        for (int nf = 0; nf < 4; nf++) {
            int nn = nh2 + nf * 8 + r0;
            bF[nf][0] = Vs[(kk + cc) * VSTR + nn];
            bF[nf][1] = Vs[(kk + cc + 4) * VSTR + nn];
        }
#pragma unroll
        for (int nf = 0; nf < 4; nf++) mma_tf32(oacc[nf], aF, bF[nf]);
    }

#pragma unroll
    for (int nf = 0; nf < 4; nf++)
#pragma unroll
        for (int rh = 0; rh < 2; rh++) {
            int i = mo + (lane >> 2) + rh * 8;
            int qi = qt * 64 + i;
            if (qi < NTOK) {
                float inv = 1.f / rowsum[i];
                int col = nh2 + nf * 8 + (lane & 3) * 2;
                *reinterpret_cast<float2*>(
                    &ao[(size_t)(w * NTOK + qi) * ED + h * HDIM + col]) =
                    make_float2(tf32r(oacc[nf][rh * 2] * inv),
                                tf32r(oacc[nf][rh * 2 + 1] * inv));
            }
        }
}

extern "C" void kernel_launch(void* const* d_in, const int* in_sizes, int n_in,
                              void* d_out, int out_size) {
    const float* x     = (const float*)d_in[0];
    const float* n1w   = (const float*)d_in[1];
    const float* n1b   = (const float*)d_in[2];
    const float* qkvw  = (const float*)d_in[3];
    const float* qkvb  = (const float*)d_in[4];
    const float* projw = (const float*)d_in[5];
    const float* projb = (const float*)d_in[6];
    const float* rph   = (const float*)d_in[7];
    const float* rpw   = (const float*)d_in[8];
    const float* n2w   = (const float*)d_in[9];
    const float* n2b   = (const float*)d_in[10];
    const float* w1    = (const float*)d_in[11];
    const float* b1    = (const float*)d_in[12];
    const float* w2    = (const float*)d_in[13];
    const float* b2    = (const float*)d_in[14];
    float* out = (float*)d_out;

    void *py, *pqkv, *px1, *phh, *pwq, *pwp, *pw1, *pw2;
    cudaGetSymbolAddress(&py, g_y);
    cudaGetSymbolAddress(&pqkv, g_qkv);
    cudaGetSymbolAddress(&px1, g_x1);
    cudaGetSymbolAddress(&phh, g_hh);
    cudaGetSymbolAddress(&pwq, g_wqkv);
    cudaGetSymbolAddress(&pwp, g_wproj);
    cudaGetSymbolAddress(&pw1, g_w1);
    cudaGetSymbolAddress(&pw2, g_w2);
    float* y  = (float*)py;    // LN1 out, later reused as LN2 out
    float* ao = (float*)phh;   // attn out lives in front of g_hh until proj consumes it

    cudaFuncSetAttribute(attn_kernel, cudaFuncAttributeMaxDynamicSharedMemorySize, ATT_SMEM);

    cvt_kernel<<<256, 256>>>(qkvw, (float*)pwq, 768 * 2304);
    cvt_kernel<<<256, 256>>>(projw, (float*)pwp, 768 * 768);
    cvt_kernel<<<256, 256>>>(w1, (float*)pw1, 768 * 3072);
    cvt_kernel<<<256, 256>>>(w2, (float*)pw2, 3072 * 768);

    ln_kernel<<<TT, 256>>>(x, n1w, n1b, y, 1);

    gemm_kernel<EPI_QKV><<<dim3(TT / BM, 2304 / BN), 256>>>(
        y, (float*)pwq, qkvb, nullptr, (float*)pqkv, TT, 2304, 768);

    attn_kernel<<<dim3(4, 128 * NHEAD), 256, ATT_SMEM>>>(rph, rpw, ao);

    gemm_kernel<EPI_PROJ><<<dim3(TT / BM, 768 / BN), 256>>>(
        ao, (float*)pwp, projb, x, (float*)px1, TT, 768, 768);

    ln_kernel<<<TT, 256>>>((float*)px1, n2w, n2b, y, 0);

    gemm_kernel<EPI_MLP1><<<dim3(TT / BM, MLPD / BN), 256>>>(
        y, (float*)pw1, b1, nullptr, (float*)phh, TT, MLPD, 768);

    gemm_kernel<EPI_MLP2><<<dim3(TT / BM, 768 / BN), 256>>>(
        (float*)phh, (float*)pw2, b2, (float*)px1, out, TT, 768, MLPD);
}

// round 11
// speedup vs baseline: 1.0641x; 1.0641x over previous
#include <cuda_runtime.h>
#include <cstdint>

#define TT    25088
#define ED    768
#define NHEAD 12
#define HDIM  64
#define NTOK  196
#define MLPD  3072

// fp32 (tf32-rounded) pipeline buffers, lifetime-aliased:
//   g_y  : LN1 out -> reused as LN2 out
//   g_hh : front TT*ED floats hold attn out until proj GEMM consumes them
__device__ float g_y  [(size_t)TT * ED];
__device__ float g_qkv[(size_t)TT * 2304];
__device__ float g_x1 [(size_t)TT * ED];
__device__ float g_hh [(size_t)TT * MLPD];
__device__ float g_wqkv [768 * 2304];
__device__ float g_wproj[768 * 768];
__device__ float g_w1   [768 * 3072];
__device__ float g_w2   [3072 * 768];

__device__ __forceinline__ uint32_t smem_u32(const void* p) {
    return (uint32_t)__cvta_generic_to_shared(p);
}
__device__ __forceinline__ float tf32r(float x) {
    asm("cvt.rna.tf32.f32 %0,%1;\n" : "=f"(x) : "f"(x));
    return x;
}
__device__ __forceinline__ void mma_tf32(float* c, const float* a, const float* b) {
    asm volatile(
        "mma.sync.aligned.m16n8k8.row.col.f32.tf32.tf32.f32 "
        "{%0,%1,%2,%3},{%4,%5,%6,%7},{%8,%9},{%0,%1,%2,%3};\n"
        : "+f"(c[0]), "+f"(c[1]), "+f"(c[2]), "+f"(c[3])
        : "r"(__float_as_uint(a[0])), "r"(__float_as_uint(a[1])),
          "r"(__float_as_uint(a[2])), "r"(__float_as_uint(a[3])),
          "r"(__float_as_uint(b[0])), "r"(__float_as_uint(b[1])));
}
__device__ __forceinline__ void cpasync16(void* s, const void* g) {
    asm volatile("cp.async.cg.shared.global [%0],[%1],16;\n" ::"r"(smem_u32(s)), "l"(g));
}
__device__ __forceinline__ void cp_commit() { asm volatile("cp.async.commit_group;\n"); }
__device__ __forceinline__ void cp_wait0()  { asm volatile("cp.async.wait_group 0;\n"); }

__device__ __forceinline__ int tok_to_winrow(int t) {
    int img = t / 3136; int rem = t - img * 3136;
    int r = rem / 56, c = rem - r * 56;
    return (img * 16 + (r / 14) * 4 + (c / 14)) * NTOK + (r % 14) * 14 + (c % 14);
}
__device__ __forceinline__ int winrow_to_tok(int rr) {
    int w = rr / NTOK, p = rr - w * NTOK;
    int img = w >> 4; int wi = w & 15;
    return img * 3136 + ((wi >> 2) * 14 + p / 14) * 56 + (wi & 3) * 14 + p % 14;
}

// single-launch weight rounding for all 4 weight matrices
#define CVT_S0 (768 * 2304)
#define CVT_S1 (768 * 768)
#define CVT_S2 (768 * 3072)
#define CVT_S3 (3072 * 768)
#define CVT_TOT (CVT_S0 + CVT_S1 + CVT_S2 + CVT_S3)
__global__ void cvt_all_kernel(const float* __restrict__ s0, const float* __restrict__ s1,
                               const float* __restrict__ s2, const float* __restrict__ s3) {
    for (int i = blockIdx.x * blockDim.x + threadIdx.x; i < CVT_TOT;
         i += gridDim.x * blockDim.x) {
        if (i < CVT_S0) g_wqkv[i] = tf32r(s0[i]);
        else if (i < CVT_S0 + CVT_S1) g_wproj[i - CVT_S0] = tf32r(s1[i - CVT_S0]);
        else if (i < CVT_S0 + CVT_S1 + CVT_S2)
            g_w1[i - CVT_S0 - CVT_S1] = tf32r(s2[i - CVT_S0 - CVT_S1]);
        else g_w2[i - CVT_S0 - CVT_S1 - CVT_S2] = tf32r(s3[i - CVT_S0 - CVT_S1 - CVT_S2]);
    }
}

__global__ __launch_bounds__(256) void ln_kernel(const float* __restrict__ x,
                                                 const float* __restrict__ w,
                                                 const float* __restrict__ b,
                                                 float* __restrict__ out, int permute) {
    int row = blockIdx.x;
    const float* xr = x + (size_t)row * ED;
    int t = threadIdx.x;
    float v0 = xr[t], v1 = xr[t + 256], v2 = xr[t + 512];
    float s = v0 + v1 + v2;
    float q = v0 * v0 + v1 * v1 + v2 * v2;
#pragma unroll
    for (int o = 16; o; o >>= 1) {
        s += __shfl_xor_sync(0xffffffffu, s, o);
        q += __shfl_xor_sync(0xffffffffu, q, o);
    }
    __shared__ float ss[8], sq[8], smu, srs;
    if ((t & 31) == 0) { ss[t >> 5] = s; sq[t >> 5] = q; }
    __syncthreads();
    if (t == 0) {
        float S = 0.f, Q = 0.f;
#pragma unroll
        for (int i = 0; i < 8; i++) { S += ss[i]; Q += sq[i]; }
        float mu = S * (1.f / ED);
        smu = mu; srs = rsqrtf(Q * (1.f / ED) - mu * mu + 1e-5f);
    }
    __syncthreads();
    float mu = smu, rs = srs;
    int drow = permute ? tok_to_winrow(row) : row;
    float* o = out + (size_t)drow * ED;
    o[t]       = tf32r((v0 - mu) * rs * w[t]       + b[t]);
    o[t + 256] = tf32r((v1 - mu) * rs * w[t + 256] + b[t + 256]);
    o[t + 512] = tf32r((v2 - mu) * rs * w[t + 512] + b[t + 512]);
}

// ------- tf32 GEMM 128x256x16, warp tile 64x64, double buffered -------
#define BM 128
#define BN 256
#define BK 16
#define ASTR 20      // 4*5  -> conflict-free: rows by lane>>2, col by lane&3
#define BSTR 264     // 8*33 -> conflict-free: rows by lane&3, col by lane>>2
#define A_ST (BM * ASTR)          // 2560 floats per stage
#define B_ST (BK * BSTR)          // 4224 floats per stage
#define GEMM_SMEM ((2 * A_ST + 2 * B_ST) * 4)  // 54272 bytes
#define EPI_QKV  0
#define EPI_PROJ 1
#define EPI_MLP1 2
#define EPI_MLP2 3

template <int EPI>
__global__ __launch_bounds__(256, 1) void gemm_kernel(
    const float* __restrict__ A, const float* __restrict__ B,
    const float* __restrict__ bias, const float* __restrict__ res,
    float* __restrict__ out, int M, int N, int K) {
    extern __shared__ float sh[];
    int bm = blockIdx.x * BM, bn = blockIdx.y * BN;
    int tid = threadIdx.x, lane = tid & 31, wid = tid >> 5;
    int wm = (wid >> 2) * 64, wn = (wid & 3) * 64;

    float acc[4][8][4];
#pragma unroll
    for (int i = 0; i < 4; i++)
#pragma unroll
        for (int j = 0; j < 8; j++)
#pragma unroll
            for (int r = 0; r < 4; r++) acc[i][j][r] = 0.f;

    auto load_tiles = [&](int k0, int st) {
        float* As = sh + st * A_ST;
        float* Bs = sh + 2 * A_ST + st * B_ST;
#pragma unroll
        for (int i = 0; i < 2; i++) {
            int c = tid * 2 + i;            // A: 128 rows x 4 chunks
            int ra = c >> 2, kc = c & 3;
            cpasync16(&As[ra * ASTR + kc * 4], A + (size_t)(bm + ra) * K + k0 + kc * 4);
        }
#pragma unroll
        for (int i = 0; i < 4; i++) {
            int c = i * 256 + tid;          // B: 16 rows x 64 chunks
            int kr = c >> 6, nc = c & 63;
            cpasync16(&Bs[kr * BSTR + nc * 4], B + (size_t)(k0 + kr) * N + bn + nc * 4);
        }
        cp_commit();
    };

    load_tiles(0, 0);
    int KT = K / BK, buf = 0;
    int r0 = lane >> 2, cc = lane & 3;
    for (int kt = 0; kt < KT; kt++) {
        cp_wait0();
        __syncthreads();
        if (kt + 1 < KT) load_tiles((kt + 1) * BK, buf ^ 1);
        float* As = sh + buf * A_ST;
        float* Bs = sh + 2 * A_ST + buf * B_ST;
#pragma unroll
        for (int kk = 0; kk < BK; kk += 8) {
            float aF[4][4], bF[8][2];
#pragma unroll
            for (int mf = 0; mf < 4; mf++) {
                int rr = wm + mf * 16 + r0;
                aF[mf][0] = As[rr * ASTR + kk + cc];
                aF[mf][1] = As[(rr + 8) * ASTR + kk + cc];
                aF[mf][2] = As[rr * ASTR + kk + cc + 4];
                aF[mf][3] = As[(rr + 8) * ASTR + kk + cc + 4];
            }
#pragma unroll
            for (int nf = 0; nf < 8; nf++) {
                int nn = wn + nf * 8 + r0;
                bF[nf][0] = Bs[(kk + cc) * BSTR + nn];
                bF[nf][1] = Bs[(kk + cc + 4) * BSTR + nn];
            }
#pragma unroll
            for (int mf = 0; mf < 4; mf++)
#pragma unroll
                for (int nf = 0; nf < 8; nf++) mma_tf32(acc[mf][nf], aF[mf], bF[nf]);
        }
        buf ^= 1;
        __syncthreads();
    }

#pragma unroll
    for (int mf = 0; mf < 4; mf++)
#pragma unroll
        for (int nf = 0; nf < 8; nf++) {
            int row0 = bm + wm + mf * 16 + (lane >> 2);
            int col = bn + wn + nf * 8 + (lane & 3) * 2;
            float bi0 = bias[col], bi1 = bias[col + 1];
#pragma unroll
            for (int h = 0; h < 2; h++) {
                int row = row0 + h * 8;
                float v0 = acc[mf][nf][h * 2 + 0] + bi0;
                float v1 = acc[mf][nf][h * 2 + 1] + bi1;
                if (EPI == EPI_QKV) {
                    *reinterpret_cast<float2*>(&out[(size_t)row * N + col]) =
                        make_float2(tf32r(v0), tf32r(v1));
                } else if (EPI == EPI_MLP1) {
                    float g0 = 0.5f * v0 * (1.f + erff(v0 * 0.70710678f));
                    float g1 = 0.5f * v1 * (1.f + erff(v1 * 0.70710678f));
                    *reinterpret_cast<float2*>(&out[(size_t)row * N + col]) =
                        make_float2(tf32r(g0), tf32r(g1));
                } else if (EPI == EPI_PROJ) {
                    size_t o = (size_t)winrow_to_tok(row) * ED + col;
                    float2 rv = *reinterpret_cast<const float2*>(res + o);
                    *reinterpret_cast<float2*>(&out[o]) = make_float2(rv.x + v0, rv.y + v1);
                } else {
                    size_t o = (size_t)row * ED + col;
                    float2 rv = *reinterpret_cast<const float2*>(res + o);
                    *reinterpret_cast<float2*>(&out[o]) = make_float2(rv.x + v0, rv.y + v1);
                }
            }
        }
}

// ---------------- fused windowed attention, tf32 (unchanged) ----------------
#define QSTR 68
#define KSTR 68
#define VSTR 72
#define PSTR 260
#define OFF_K   (64 * QSTR * 4)
#define OFF_V   (OFF_K + 256 * KSTR * 4)
#define OFF_RH  (OFF_V + 256 * VSTR * 4)
#define OFF_RW  (OFF_RH + 64 * 14 * 4)
#define OFF_RED (OFF_RW + 64 * 14 * 4)
#define OFF_RM  (OFF_RED + 64 * 8 * 4)
#define OFF_RS  (OFF_RM + 64 * 4)
#define ATT_SMEM (OFF_RS + 64 * 4)

__global__ __launch_bounds__(256) void attn_kernel(const float* __restrict__ relh_tab,
                                                   const float* __restrict__ relw_tab,
                                                   float* __restrict__ ao) {
    extern __shared__ char smem[];
    float* Qs = (float*)smem;
    float* Ks = (float*)(smem + OFF_K);
    float* Vs = (float*)(smem + OFF_V);
    float* relh = (float*)(smem + OFF_RH);
    float* relw = (float*)(smem + OFF_RW);
    float* red = (float*)(smem + OFF_RED);
    float* rowmax = (float*)(smem + OFF_RM);
    float* rowsum = (float*)(smem + OFF_RS);
    float* Ps = Ks;

    int qt = blockIdx.x, wh = blockIdx.y;
    int w = wh / NHEAD, h = wh - w * NHEAD;
    int tid = threadIdx.x, lane = tid & 31, wid = tid >> 5;
    size_t base = (size_t)w * NTOK * 2304 + h * HDIM;

    for (int c = tid; c < 1024; c += 256) {
        int r = c >> 4, ch = c & 15;
        int qi = qt * 64 + r;
        float4 val = make_float4(0.f, 0.f, 0.f, 0.f);
        if (qi < NTOK)
            val = *reinterpret_cast<const float4*>(&g_qkv[base + (size_t)qi * 2304 + ch * 4]);
        *reinterpret_cast<float4*>(&Qs[r * QSTR + ch * 4]) = val;
    }
    for (int c = tid; c < 4096; c += 256) {
        int r = c >> 4, ch = c & 15;
        float4 kv = make_float4(0.f, 0.f, 0.f, 0.f), vv = kv;
        if (r < NTOK) {
            kv = *reinterpret_cast<const float4*>(&g_qkv[base + (size_t)r * 2304 + 768 + ch * 4]);
            vv = *reinterpret_cast<const float4*>(&g_qkv[base + (size_t)r * 2304 + 1536 + ch * 4]);
        }
        *reinterpret_cast<float4*>(&Ks[r * KSTR + ch * 4]) = kv;
        *reinterpret_cast<float4*>(&Vs[r * VSTR + ch * 4]) = vv;
    }
    __syncthreads();

    for (int id = tid; id < 1792; id += 256) {
        int tab = id >= 896;
        int lid = tab ? id - 896 : id;
        int i = lid / 14, kx = lid - 14 * i;
        int qi = qt * 64 + i;
        float sum = 0.f;
        if (qi < NTOK) {
            int qh = qi / 14, qw = qi - qh * 14;
            int ridx = (tab ? qw : qh) - kx + 13;
            const float* tp = (tab ? relw_tab : relh_tab) + ridx * HDIM;
#pragma unroll 8
            for (int d = 0; d < HDIM; d++) sum += Qs[i * QSTR + d] * tp[d];
        }
        (tab ? relw : relh)[i * 14 + kx] = sum;
    }
    __syncthreads();

    float sacc[4][4][4];
#pragma unroll
    for (int i = 0; i < 4; i++)
#pragma unroll
        for (int j = 0; j < 4; j++)
#pragma unroll
            for (int r = 0; r < 4; r++) sacc[i][j][r] = 0.f;
    int n0 = wid * 32;
    int r0 = lane >> 2, cc = lane & 3;
#pragma unroll
    for (int kk = 0; kk < HDIM; kk += 8) {
        float aF[4][4], bF[4][2];
#pragma unroll
        for (int mf = 0; mf < 4; mf++) {
            int rr = mf * 16 + r0;
            aF[mf][0] = Qs[rr * QSTR + kk + cc];
            aF[mf][1] = Qs[(rr + 8) * QSTR + kk + cc];
            aF[mf][2] = Qs[rr * QSTR + kk + cc + 4];
            aF[mf][3] = Qs[(rr + 8) * QSTR + kk + cc + 4];
        }
#pragma unroll
        for (int nf = 0; nf < 4; nf++) {
            int key = n0 + nf * 8 + r0;
            bF[nf][0] = Ks[key * KSTR + kk + cc];
            bF[nf][1] = Ks[key * KSTR + kk + cc + 4];
        }
#pragma unroll
        for (int mf = 0; mf < 4; mf++)
#pragma unroll
            for (int nf = 0; nf < 4; nf++) mma_tf32(sacc[mf][nf], aF[mf], bF[nf]);
    }

    const float scale = 0.125f;
#pragma unroll
    for (int mf = 0; mf < 4; mf++)
#pragma unroll
        for (int nf = 0; nf < 4; nf++)
#pragma unroll
            for (int r = 0; r < 4; r++) {
                int i = mf * 16 + (lane >> 2) + (r >> 1) * 8;
                int j = n0 + nf * 8 + (lane & 3) * 2 + (r & 1);
                float s;
                if (j < NTOK) {
                    int kh = j / 14, kw = j - kh * 14;
                    s = sacc[mf][nf][r] * scale + relh[i * 14 + kh] + relw[i * 14 + kw];
                } else s = -1e30f;
                sacc[mf][nf][r] = s;
            }

#pragma unroll
    for (int mf = 0; mf < 4; mf++)
#pragma unroll
        for (int rh = 0; rh < 2; rh++) {
            float m = -1e30f;
#pragma unroll
            for (int nf = 0; nf < 4; nf++) {
                m = fmaxf(m, sacc[mf][nf][rh * 2]);
                m = fmaxf(m, sacc[mf][nf][rh * 2 + 1]);
            }
            m = fmaxf(m, __shfl_xor_sync(0xffffffffu, m, 1));
            m = fmaxf(m, __shfl_xor_sync(0xffffffffu, m, 2));
            if ((lane & 3) == 0) red[(mf * 16 + (lane >> 2) + rh * 8) * 8 + wid] = m;
        }
    __syncthreads();
    if (tid < 64) {
        float m = red[tid * 8];
#pragma unroll
        for (int k = 1; k < 8; k++) m = fmaxf(m, red[tid * 8 + k]);
        rowmax[tid] = m;
    }
    __syncthreads();

#pragma unroll
    for (int mf = 0; mf < 4; mf++)
#pragma unroll
        for (int rh = 0; rh < 2; rh++) {
            int i = mf * 16 + (lane >> 2) + rh * 8;
            float rm = rowmax[i], s = 0.f;
#pragma unroll
            for (int nf = 0; nf < 4; nf++) {
                float p0 = __expf(sacc[mf][nf][rh * 2] - rm);
                float p1 = __expf(sacc[mf][nf][rh * 2 + 1] - rm);
                s += p0 + p1;
                int j = n0 + nf * 8 + (lane & 3) * 2;
                *reinterpret_cast<float2*>(&Ps[i * PSTR + j]) =
                    make_float2(tf32r(p0), tf32r(p1));
            }
            s += __shfl_xor_sync(0xffffffffu, s, 1);
            s += __shfl_xor_sync(0xffffffffu, s, 2);
            if ((lane & 3) == 0) red[i * 8 + wid] = s;
        }
    __syncthreads();
    if (tid < 64) {
        float s = 0.f;
#pragma unroll
        for (int k = 0; k < 8; k++) s += red[tid * 8 + k];
        rowsum[tid] = s;
    }
    __syncthreads();

    float oacc[4][4];
#pragma unroll
    for (int i = 0; i < 4; i++)
#pragma unroll
        for (int r = 0; r < 4; r++) oacc[i][r] = 0.f;
    int mo = (wid & 3) * 16, nh2 = (wid >> 2) * 32;
#pragma unroll 8
    for (int kk = 0; kk < 256; kk += 8) {
        float aF[4], bF[4][2];
        int rr = mo + r0;
        aF[0] = Ps[rr * PSTR + kk + cc];
        aF[1] = Ps[(rr + 8) * PSTR + kk + cc];
        aF[2] = Ps[rr * PSTR + kk + cc + 4];
        aF[3] = Ps[(rr + 8) * PSTR + kk + cc + 4];
#pragma unroll
        for (int nf = 0; nf < 4; nf++) {
            int nn = nh2 + nf * 8 + r0;
            bF[nf][0] = Vs[(kk + cc) * VSTR + nn];
            bF[nf][1] = Vs[(kk + cc + 4) * VSTR + nn];
        }
#pragma unroll
        for (int nf = 0; nf < 4; nf++) mma_tf32(oacc[nf], aF, bF[nf]);
    }

#pragma unroll
    for (int nf = 0; nf < 4; nf++)
#pragma unroll
        for (int rh = 0; rh < 2; rh++) {
            int i = mo + (lane >> 2) + rh * 8;
            int qi = qt * 64 + i;
            if (qi < NTOK) {
                float inv = 1.f / rowsum[i];
                int col = nh2 + nf * 8 + (lane & 3) * 2;
                *reinterpret_cast<float2*>(
                    &ao[(size_t)(w * NTOK + qi) * ED + h * HDIM + col]) =
                    make_float2(tf32r(oacc[nf][rh * 2] * inv),
                                tf32r(oacc[nf][rh * 2 + 1] * inv));
            }
        }
}

extern "C" void kernel_launch(void* const* d_in, const int* in_sizes, int n_in,
                              void* d_out, int out_size) {
    const float* x     = (const float*)d_in[0];
    const float* n1w   = (const float*)d_in[1];
    const float* n1b   = (const float*)d_in[2];
    const float* qkvw  = (const float*)d_in[3];
    const float* qkvb  = (const float*)d_in[4];
    const float* projw = (const float*)d_in[5];
    const float* projb = (const float*)d_in[6];
    const float* rph   = (const float*)d_in[7];
    const float* rpw   = (const float*)d_in[8];
    const float* n2w   = (const float*)d_in[9];
    const float* n2b   = (const float*)d_in[10];
    const float* w1    = (const float*)d_in[11];
    const float* b1    = (const float*)d_in[12];
    const float* w2    = (const float*)d_in[13];
    const float* b2    = (const float*)d_in[14];
    float* out = (float*)d_out;

    void *py, *pqkv, *px1, *phh, *pwq, *pwp, *pw1, *pw2;
    cudaGetSymbolAddress(&py, g_y);
    cudaGetSymbolAddress(&pqkv, g_qkv);
    cudaGetSymbolAddress(&px1, g_x1);
    cudaGetSymbolAddress(&phh, g_hh);
    cudaGetSymbolAddress(&pwq, g_wqkv);
    cudaGetSymbolAddress(&pwp, g_wproj);
    cudaGetSymbolAddress(&pw1, g_w1);
    cudaGetSymbolAddress(&pw2, g_w2);
    float* y  = (float*)py;
    float* ao = (float*)phh;

    cudaFuncSetAttribute(attn_kernel, cudaFuncAttributeMaxDynamicSharedMemorySize, ATT_SMEM);
    cudaFuncSetAttribute(gemm_kernel<EPI_QKV>,
                         cudaFuncAttributeMaxDynamicSharedMemorySize, GEMM_SMEM);
    cudaFuncSetAttribute(gemm_kernel<EPI_PROJ>,
                         cudaFuncAttributeMaxDynamicSharedMemorySize, GEMM_SMEM);
    cudaFuncSetAttribute(gemm_kernel<EPI_MLP1>,
                         cudaFuncAttributeMaxDynamicSharedMemorySize, GEMM_SMEM);
    cudaFuncSetAttribute(gemm_kernel<EPI_MLP2>,
                         cudaFuncAttributeMaxDynamicSharedMemorySize, GEMM_SMEM);

    cvt_all_kernel<<<512, 256>>>(qkvw, projw, w1, w2);

    ln_kernel<<<TT, 256>>>(x, n1w, n1b, y, 1);

    gemm_kernel<EPI_QKV><<<dim3(TT / BM, 2304 / BN), 256, GEMM_SMEM>>>(
        y, (float*)pwq, qkvb, nullptr, (float*)pqkv, TT, 2304, 768);

    attn_kernel<<<dim3(4, 128 * NHEAD), 256, ATT_SMEM>>>(rph, rpw, ao);

    gemm_kernel<EPI_PROJ><<<dim3(TT / BM, 768 / BN), 256, GEMM_SMEM>>>(
        ao, (float*)pwp, projb, x, (float*)px1, TT, 768, 768);

    ln_kernel<<<TT, 256>>>((float*)px1, n2w, n2b, y, 0);

    gemm_kernel<EPI_MLP1><<<dim3(TT / BM, MLPD / BN), 256, GEMM_SMEM>>>(
        y, (float*)pw1, b1, nullptr, (float*)phh, TT, MLPD, 768);

    gemm_kernel<EPI_MLP2><<<dim3(TT / BM, 768 / BN), 256, GEMM_SMEM>>>(
        (float*)phh, (float*)pw2, b2, (float*)px1, out, TT, 768, MLPD);
}

// round 13
// speedup vs baseline: 1.7974x; 1.6891x over previous
#include <cuda_runtime.h>
#include <cuda_fp16.h>
#include <cstdint>

#define TT    25088
#define ED    768
#define NHEAD 12
#define HDIM  64
#define NTOK  196
#define MLPD  3072

// fp16 activations / weights, fp32 residual path. Lifetime-aliased:
//   g_y  : LN1 out -> reused as LN2 out
//   g_hh : front TT*ED halves hold attn out until proj GEMM consumes them
__device__ __half g_y  [(size_t)TT * ED];
__device__ __half g_qkv[(size_t)TT * 2304];
__device__ float  g_x1 [(size_t)TT * ED];
__device__ __half g_hh [(size_t)TT * MLPD];
__device__ __half g_wqkv [768 * 2304];
__device__ __half g_wproj[768 * 768];
__device__ __half g_w1   [768 * 3072];
__device__ __half g_w2   [3072 * 768];

__device__ __forceinline__ uint32_t smem_u32(const void* p) {
    return (uint32_t)__cvta_generic_to_shared(p);
}
__device__ __forceinline__ void ldsm4(uint32_t& r0, uint32_t& r1, uint32_t& r2, uint32_t& r3,
                                      uint32_t a) {
    asm volatile("ldmatrix.sync.aligned.m8n8.x4.shared.b16 {%0,%1,%2,%3},[%4];\n"
                 : "=r"(r0), "=r"(r1), "=r"(r2), "=r"(r3) : "r"(a));
}
__device__ __forceinline__ void ldsm4t(uint32_t& r0, uint32_t& r1, uint32_t& r2, uint32_t& r3,
                                       uint32_t a) {
    asm volatile("ldmatrix.sync.aligned.m8n8.x4.trans.shared.b16 {%0,%1,%2,%3},[%4];\n"
                 : "=r"(r0), "=r"(r1), "=r"(r2), "=r"(r3) : "r"(a));
}
__device__ __forceinline__ void mma16816(float* c, const uint32_t* a, const uint32_t* b) {
    asm volatile(
        "mma.sync.aligned.m16n8k16.row.col.f32.f16.f16.f32 "
        "{%0,%1,%2,%3},{%4,%5,%6,%7},{%8,%9},{%0,%1,%2,%3};\n"
        : "+f"(c[0]), "+f"(c[1]), "+f"(c[2]), "+f"(c[3])
        : "r"(a[0]), "r"(a[1]), "r"(a[2]), "r"(a[3]), "r"(b[0]), "r"(b[1]));
}
__device__ __forceinline__ void cpasync16(void* s, const void* g) {
    asm volatile("cp.async.cg.shared.global [%0],[%1],16;\n" ::"r"(smem_u32(s)), "l"(g));
}
__device__ __forceinline__ void cp_commit() { asm volatile("cp.async.commit_group;\n"); }
__device__ __forceinline__ void cp_wait0()  { asm volatile("cp.async.wait_group 0;\n"); }

__device__ __forceinline__ int tok_to_winrow(int t) {
    int img = t / 3136; int rem = t - img * 3136;
    int r = rem / 56, c = rem - r * 56;
    return (img * 16 + (r / 14) * 4 + (c / 14)) * NTOK + (r % 14) * 14 + (c % 14);
}
__device__ __forceinline__ int winrow_to_tok(int rr) {
    int w = rr / NTOK, p = rr - w * NTOK;
    int img = w >> 4; int wi = w & 15;
    return img * 3136 + ((wi >> 2) * 14 + p / 14) * 56 + (wi & 3) * 14 + p % 14;
}

// single-launch fp32 -> fp16 weight conversion for all 4 weight matrices
#define CVT_S0 (768 * 2304)
#define CVT_S1 (768 * 768)
#define CVT_S2 (768 * 3072)
#define CVT_S3 (3072 * 768)
#define CVT_TOT (CVT_S0 + CVT_S1 + CVT_S2 + CVT_S3)
__global__ void cvt_all_kernel(const float* __restrict__ s0, const float* __restrict__ s1,
                               const float* __restrict__ s2, const float* __restrict__ s3) {
    for (int i = blockIdx.x * blockDim.x + threadIdx.x; i < CVT_TOT;
         i += gridDim.x * blockDim.x) {
        if (i < CVT_S0) g_wqkv[i] = __float2half_rn(s0[i]);
        else if (i < CVT_S0 + CVT_S1) g_wproj[i - CVT_S0] = __float2half_rn(s1[i - CVT_S0]);
        else if (i < CVT_S0 + CVT_S1 + CVT_S2)
            g_w1[i - CVT_S0 - CVT_S1] = __float2half_rn(s2[i - CVT_S0 - CVT_S1]);
        else g_w2[i - CVT_S0 - CVT_S1 - CVT_S2] =
            __float2half_rn(s3[i - CVT_S0 - CVT_S1 - CVT_S2]);
    }
}

__global__ __launch_bounds__(256) void ln_kernel(const float* __restrict__ x,
                                                 const float* __restrict__ w,
                                                 const float* __restrict__ b,
                                                 __half* __restrict__ out, int permute) {
    int row = blockIdx.x;
    const float* xr = x + (size_t)row * ED;
    int t = threadIdx.x;
    float v0 = xr[t], v1 = xr[t + 256], v2 = xr[t + 512];
    float s = v0 + v1 + v2;
    float q = v0 * v0 + v1 * v1 + v2 * v2;
#pragma unroll
    for (int o = 16; o; o >>= 1) {
        s += __shfl_xor_sync(0xffffffffu, s, o);
        q += __shfl_xor_sync(0xffffffffu, q, o);
    }
    __shared__ float ss[8], sq[8], smu, srs;
    if ((t & 31) == 0) { ss[t >> 5] = s; sq[t >> 5] = q; }
    __syncthreads();
    if (t == 0) {
        float S = 0.f, Q = 0.f;
#pragma unroll
        for (int i = 0; i < 8; i++) { S += ss[i]; Q += sq[i]; }
        float mu = S * (1.f / ED);
        smu = mu; srs = rsqrtf(Q * (1.f / ED) - mu * mu + 1e-5f);
    }
    __syncthreads();
    float mu = smu, rs = srs;
    int drow = permute ? tok_to_winrow(row) : row;
    __half* o = out + (size_t)drow * ED;
    o[t]       = __float2half_rn((v0 - mu) * rs * w[t]       + b[t]);
    o[t + 256] = __float2half_rn((v1 - mu) * rs * w[t + 256] + b[t + 256]);
    o[t + 512] = __float2half_rn((v2 - mu) * rs * w[t + 512] + b[t + 512]);
}

// ---------- fp16 GEMM 128x128x32, double buffered (R7 structure) ----------
#define BM 128
#define BN 128
#define BKT 32
#define EPI_QKV  0
#define EPI_PROJ 1
#define EPI_MLP1 2
#define EPI_MLP2 3

template <int EPI>
__global__ __launch_bounds__(256) void gemm_kernel(
    const __half* __restrict__ A, const __half* __restrict__ B,
    const float* __restrict__ bias, const float* __restrict__ res,
    float* __restrict__ outf, __half* __restrict__ outh, int M, int N, int K) {
    __shared__ __align__(16) __half a_s[2][BM][40];
    __shared__ __align__(16) __half b_s[2][BKT][136];
    int bm = blockIdx.x * BM, bn = blockIdx.y * BN;
    int tid = threadIdx.x, lane = tid & 31, wid = tid >> 5;
    int wm = (wid >> 2) * 64, wn = (wid & 3) * 32;

    float acc[4][4][4];
#pragma unroll
    for (int i = 0; i < 4; i++)
#pragma unroll
        for (int j = 0; j < 4; j++)
#pragma unroll
            for (int r = 0; r < 4; r++) acc[i][j][r] = 0.f;

    auto load_tiles = [&](int k0, int buf) {
#pragma unroll
        for (int i = 0; i < 2; i++) {
            int c = tid * 2 + i;
            int ra = c >> 2, kc = c & 3;
            cpasync16(&a_s[buf][ra][kc * 8], A + (size_t)(bm + ra) * K + k0 + kc * 8);
        }
#pragma unroll
        for (int i = 0; i < 2; i++) {
            int c = tid * 2 + i;
            int kr = c >> 4, nc = c & 15;
            cpasync16(&b_s[buf][kr][nc * 8], B + (size_t)(k0 + kr) * N + bn + nc * 8);
        }
        cp_commit();
    };

    load_tiles(0, 0);
    int KT = K / BKT, buf = 0;
    for (int kt = 0; kt < KT; kt++) {
        cp_wait0();
        __syncthreads();
        if (kt + 1 < KT) load_tiles((kt + 1) * BKT, buf ^ 1);
#pragma unroll
        for (int kk = 0; kk < BKT; kk += 16) {
            uint32_t af[4][4], bf[4][2];
#pragma unroll
            for (int mf = 0; mf < 4; mf++) {
                uint32_t a = smem_u32(&a_s[buf][wm + mf * 16 + (lane & 15)]
                                          [kk + (lane >> 4) * 8]);
                ldsm4(af[mf][0], af[mf][1], af[mf][2], af[mf][3], a);
            }
#pragma unroll
            for (int nf2 = 0; nf2 < 2; nf2++) {
                uint32_t r0, r1, r2, r3;
                uint32_t a = smem_u32(&b_s[buf][kk + ((lane >> 3) & 1) * 8 + (lane & 7)]
                                          [wn + nf2 * 16 + (lane >> 4) * 8]);
                ldsm4t(r0, r1, r2, r3, a);
                bf[nf2 * 2][0] = r0; bf[nf2 * 2][1] = r1;
                bf[nf2 * 2 + 1][0] = r2; bf[nf2 * 2 + 1][1] = r3;
            }
#pragma unroll
            for (int mf = 0; mf < 4; mf++)
#pragma unroll
                for (int nf = 0; nf < 4; nf++) mma16816(acc[mf][nf], af[mf], bf[nf]);
        }
        buf ^= 1;
        __syncthreads();
    }

#pragma unroll
    for (int mf = 0; mf < 4; mf++)
#pragma unroll
        for (int nf = 0; nf < 4; nf++) {
            int row0 = bm + wm + mf * 16 + (lane >> 2);
            int col = bn + wn + nf * 8 + (lane & 3) * 2;
            float bi0 = bias[col], bi1 = bias[col + 1];
#pragma unroll
            for (int h = 0; h < 2; h++) {
                int row = row0 + h * 8;
                float v0 = acc[mf][nf][h * 2 + 0] + bi0;
                float v1 = acc[mf][nf][h * 2 + 1] + bi1;
                if (EPI == EPI_QKV) {
                    *reinterpret_cast<__half2*>(&outh[(size_t)row * N + col]) =
                        __floats2half2_rn(v0, v1);
                } else if (EPI == EPI_MLP1) {
                    float g0 = 0.5f * v0 * (1.f + erff(v0 * 0.70710678f));
                    float g1 = 0.5f * v1 * (1.f + erff(v1 * 0.70710678f));
                    *reinterpret_cast<__half2*>(&outh[(size_t)row * N + col]) =
                        __floats2half2_rn(g0, g1);
                } else if (EPI == EPI_PROJ) {
                    size_t o = (size_t)winrow_to_tok(row) * ED + col;
                    float2 rv = *reinterpret_cast<const float2*>(res + o);
                    *reinterpret_cast<float2*>(&outf[o]) = make_float2(rv.x + v0, rv.y + v1);
                } else {
                    size_t o = (size_t)row * ED + col;
                    float2 rv = *reinterpret_cast<const float2*>(res + o);
                    *reinterpret_cast<float2*>(&outf[o]) = make_float2(rv.x + v0, rv.y + v1);
                }
            }
        }
}

// ---------------- fused windowed attention, fp16 ----------------
#define QLD 72
#define PLD 264
#define OFF_K   (64 * QLD * 2)
#define OFF_V   (OFF_K + 256 * QLD * 2)
#define OFF_RH  (OFF_V + 256 * QLD * 2)
#define OFF_RW  (OFF_RH + 64 * 14 * 4)
#define OFF_RED (OFF_RW + 64 * 14 * 4)
#define OFF_RM  (OFF_RED + 64 * 8 * 4)
#define OFF_RS  (OFF_RM + 64 * 4)
#define ATT_SMEM (OFF_RS + 64 * 4)

__global__ __launch_bounds__(256) void attn_kernel(const float* __restrict__ relh_tab,
                                                   const float* __restrict__ relw_tab,
                                                   __half* __restrict__ ao) {
    extern __shared__ char smem[];
    __half* Qs = (__half*)smem;
    __half* Ks = (__half*)(smem + OFF_K);
    __half* Vs = (__half*)(smem + OFF_V);
    float* relh = (float*)(smem + OFF_RH);
    float* relw = (float*)(smem + OFF_RW);
    float* red = (float*)(smem + OFF_RED);
    float* rowmax = (float*)(smem + OFF_RM);
    float* rowsum = (float*)(smem + OFF_RS);
    __half* Ps = Ks;  // 64*264 halves <= 256*72 halves

    int qt = blockIdx.x, wh = blockIdx.y;
    int w = wh / NHEAD, h = wh - w * NHEAD;
    int tid = threadIdx.x, lane = tid & 31, wid = tid >> 5;
    size_t base = (size_t)w * NTOK * 2304 + h * HDIM;

    for (int c = tid; c < 512; c += 256) {
        int r = c >> 3, ch = c & 7;
        int qi = qt * 64 + r;
        uint4 val = make_uint4(0, 0, 0, 0);
        if (qi < NTOK)
            val = *reinterpret_cast<const uint4*>(&g_qkv[base + (size_t)qi * 2304 + ch * 8]);
        *reinterpret_cast<uint4*>(&Qs[r * QLD + ch * 8]) = val;
    }
    for (int c = tid; c < 2048; c += 256) {
        int r = c >> 3, ch = c & 7;
        uint4 kv = make_uint4(0, 0, 0, 0), vv = make_uint4(0, 0, 0, 0);
        if (r < NTOK) {
            kv = *reinterpret_cast<const uint4*>(&g_qkv[base + (size_t)r * 2304 + 768 + ch * 8]);
            vv = *reinterpret_cast<const uint4*>(&g_qkv[base + (size_t)r * 2304 + 1536 + ch * 8]);
        }
        *reinterpret_cast<uint4*>(&Ks[r * QLD + ch * 8]) = kv;
        *reinterpret_cast<uint4*>(&Vs[r * QLD + ch * 8]) = vv;
    }
    __syncthreads();

    // decomposed rel-pos: relh[i][kh] = q_i . Rh[qh-kh+13], relw analogous
    for (int id = tid; id < 1792; id += 256) {
        int tab = id >= 896;
        int lid = tab ? id - 896 : id;
        int i = lid / 14, kx = lid - 14 * i;
        int qi = qt * 64 + i;
        float sum = 0.f;
        if (qi < NTOK) {
            int qh = qi / 14, qw = qi - qh * 14;
            int ridx = (tab ? qw : qh) - kx + 13;
            const float* tp = (tab ? relw_tab : relh_tab) + ridx * HDIM;
#pragma unroll 8
            for (int d = 0; d < HDIM; d++) sum += __half2float(Qs[i * QLD + d]) * tp[d];
        }
        (tab ? relw : relh)[i * 14 + kx] = sum;
    }
    __syncthreads();

    // S = Q K^T
    float sacc[4][4][4];
#pragma unroll
    for (int i = 0; i < 4; i++)
#pragma unroll
        for (int j = 0; j < 4; j++)
#pragma unroll
            for (int r = 0; r < 4; r++) sacc[i][j][r] = 0.f;
    int n0 = wid * 32;
#pragma unroll
    for (int kk = 0; kk < HDIM; kk += 16) {
        uint32_t af[4][4], bf[4][2];
#pragma unroll
        for (int mf = 0; mf < 4; mf++) {
            uint32_t a = smem_u32(&Qs[(mf * 16 + (lane & 15)) * QLD + kk + (lane >> 4) * 8]);
            ldsm4(af[mf][0], af[mf][1], af[mf][2], af[mf][3], a);
        }
#pragma unroll
        for (int nf2 = 0; nf2 < 2; nf2++) {
            uint32_t r0, r1, r2, r3;
            uint32_t a = smem_u32(&Ks[(n0 + nf2 * 16 + (lane >> 4) * 8 + (lane & 7)) * QLD +
                                      kk + ((lane >> 3) & 1) * 8]);
            ldsm4(r0, r1, r2, r3, a);
            bf[nf2 * 2][0] = r0; bf[nf2 * 2][1] = r1;
            bf[nf2 * 2 + 1][0] = r2; bf[nf2 * 2 + 1][1] = r3;
        }
#pragma unroll
        for (int mf = 0; mf < 4; mf++)
#pragma unroll
            for (int nf = 0; nf < 4; nf++) mma16816(sacc[mf][nf], af[mf], bf[nf]);
    }

    const float scale = 0.125f;
#pragma unroll
    for (int mf = 0; mf < 4; mf++)
#pragma unroll
        for (int nf = 0; nf < 4; nf++)
#pragma unroll
            for (int r = 0; r < 4; r++) {
                int i = mf * 16 + (lane >> 2) + (r >> 1) * 8;
                int j = n0 + nf * 8 + (lane & 3) * 2 + (r & 1);
                float s;
                if (j < NTOK) {
                    int kh = j / 14, kw = j - kh * 14;
                    s = sacc[mf][nf][r] * scale + relh[i * 14 + kh] + relw[i * 14 + kw];
                } else s = -1e30f;
                sacc[mf][nf][r] = s;
            }

#pragma unroll
    for (int mf = 0; mf < 4; mf++)
#pragma unroll
        for (int rh = 0; rh < 2; rh++) {
            float m = -1e30f;
#pragma unroll
            for (int nf = 0; nf < 4; nf++) {
                m = fmaxf(m, sacc[mf][nf][rh * 2]);
                m = fmaxf(m, sacc[mf][nf][rh * 2 + 1]);
            }
            m = fmaxf(m, __shfl_xor_sync(0xffffffffu, m, 1));
            m = fmaxf(m, __shfl_xor_sync(0xffffffffu, m, 2));
            if ((lane & 3) == 0) red[(mf * 16 + (lane >> 2) + rh * 8) * 8 + wid] = m;
        }
    __syncthreads();
    if (tid < 64) {
        float m = red[tid * 8];
#pragma unroll
        for (int k = 1; k < 8; k++) m = fmaxf(m, red[tid * 8 + k]);
        rowmax[tid] = m;
    }
    __syncthreads();

#pragma unroll
    for (int mf = 0; mf < 4; mf++)
#pragma unroll
        for (int rh = 0; rh < 2; rh++) {
            int i = mf * 16 + (lane >> 2) + rh * 8;
            float rm = rowmax[i], s = 0.f;
#pragma unroll
            for (int nf = 0; nf < 4; nf++) {
                float p0 = __expf(sacc[mf][nf][rh * 2] - rm);
                float p1 = __expf(sacc[mf][nf][rh * 2 + 1] - rm);
                s += p0 + p1;
                int j = n0 + nf * 8 + (lane & 3) * 2;
                *reinterpret_cast<__half2*>(&Ps[i * PLD + j]) = __floats2half2_rn(p0, p1);
            }
            s += __shfl_xor_sync(0xffffffffu, s, 1);
            s += __shfl_xor_sync(0xffffffffu, s, 2);
            if ((lane & 3) == 0) red[i * 8 + wid] = s;
        }
    __syncthreads();
    if (tid < 64) {
        float s = 0.f;
#pragma unroll
        for (int k = 0; k < 8; k++) s += red[tid * 8 + k];
        rowsum[tid] = s;
    }
    __syncthreads();

    // O = P @ V
    float oacc[4][4];
#pragma unroll
    for (int i = 0; i < 4; i++)
#pragma unroll
        for (int r = 0; r < 4; r++) oacc[i][r] = 0.f;
    int mo = (wid & 3) * 16, nh2 = (wid >> 2) * 32;
#pragma unroll
    for (int kk = 0; kk < 256; kk += 16) {
        uint32_t af[4], bf[4][2];
        uint32_t aa = smem_u32(&Ps[(mo + (lane & 15)) * PLD + kk + (lane >> 4) * 8]);
        ldsm4(af[0], af[1], af[2], af[3], aa);
#pragma unroll
        for (int nf2 = 0; nf2 < 2; nf2++) {
            uint32_t r0, r1, r2, r3;
            uint32_t a = smem_u32(&Vs[(kk + ((lane >> 3) & 1) * 8 + (lane & 7)) * QLD +
                                      nh2 + nf2 * 16 + (lane >> 4) * 8]);
            ldsm4t(r0, r1, r2, r3, a);
            bf[nf2 * 2][0] = r0; bf[nf2 * 2][1] = r1;
            bf[nf2 * 2 + 1][0] = r2; bf[nf2 * 2 + 1][1] = r3;
        }
#pragma unroll
        for (int nf = 0; nf < 4; nf++) mma16816(oacc[nf], af, bf[nf]);
    }

#pragma unroll
    for (int nf = 0; nf < 4; nf++)
#pragma unroll
        for (int rh = 0; rh < 2; rh++) {
            int i = mo + (lane >> 2) + rh * 8;
            int qi = qt * 64 + i;
            if (qi < NTOK) {
                float inv = 1.f / rowsum[i];
                int col = nh2 + nf * 8 + (lane & 3) * 2;
                *reinterpret_cast<__half2*>(
                    &ao[(size_t)(w * NTOK + qi) * ED + h * HDIM + col]) =
                    __floats2half2_rn(oacc[nf][rh * 2] * inv, oacc[nf][rh * 2 + 1] * inv);
            }
        }
}

extern "C" void kernel_launch(void* const* d_in, const int* in_sizes, int n_in,
                              void* d_out, int out_size) {
    const float* x     = (const float*)d_in[0];
    const float* n1w   = (const float*)d_in[1];
    const float* n1b   = (const float*)d_in[2];
    const float* qkvw  = (const float*)d_in[3];
    const float* qkvb  = (const float*)d_in[4];
    const float* projw = (const float*)d_in[5];
    const float* projb = (const float*)d_in[6];
    const float* rph   = (const float*)d_in[7];
    const float* rpw   = (const float*)d_in[8];
    const float* n2w   = (const float*)d_in[9];
    const float* n2b   = (const float*)d_in[10];
    const float* w1    = (const float*)d_in[11];
    const float* b1    = (const float*)d_in[12];
    const float* w2    = (const float*)d_in[13];
    const float* b2    = (const float*)d_in[14];
    float* out = (float*)d_out;

    void *py, *pqkv, *px1, *phh, *pwq, *pwp, *pw1, *pw2;
    cudaGetSymbolAddress(&py, g_y);
    cudaGetSymbolAddress(&pqkv, g_qkv);
    cudaGetSymbolAddress(&px1, g_x1);
    cudaGetSymbolAddress(&phh, g_hh);
    cudaGetSymbolAddress(&pwq, g_wqkv);
    cudaGetSymbolAddress(&pwp, g_wproj);
    cudaGetSymbolAddress(&pw1, g_w1);
    cudaGetSymbolAddress(&pw2, g_w2);
    __half* y  = (__half*)py;
    __half* ao = (__half*)phh;  // attn out aliases front of g_hh

    cudaFuncSetAttribute(attn_kernel, cudaFuncAttributeMaxDynamicSharedMemorySize, ATT_SMEM);

    cvt_all_kernel<<<512, 256>>>(qkvw, projw, w1, w2);

    ln_kernel<<<TT, 256>>>(x, n1w, n1b, y, 1);

    gemm_kernel<EPI_QKV><<<dim3(TT / BM, 2304 / BN), 256>>>(
        y, (__half*)pwq, qkvb, nullptr, nullptr, (__half*)pqkv, TT, 2304, 768);

    attn_kernel<<<dim3(4, 128 * NHEAD), 256, ATT_SMEM>>>(rph, rpw, ao);

    gemm_kernel<EPI_PROJ><<<dim3(TT / BM, 768 / BN), 256>>>(
        ao, (__half*)pwp, projb, x, (float*)px1, nullptr, TT, 768, 768);

    ln_kernel<<<TT, 256>>>((float*)px1, n2w, n2b, y, 0);

    gemm_kernel<EPI_MLP1><<<dim3(TT / BM, MLPD / BN), 256>>>(
        y, (__half*)pw1, b1, nullptr, nullptr, (__half*)phh, TT, MLPD, 768);

    gemm_kernel<EPI_MLP2><<<dim3(TT / BM, 768 / BN), 256>>>(
        (__half*)phh, (__half*)pw2, b2, (float*)px1, out, nullptr, TT, 768, MLPD);
}